// round 5
// baseline (speedup 1.0000x reference)
#include <cuda_runtime.h>

// Per-row L2 normalization, persistent-CTA software-pipelined version.
// 16384 rows x 4096 cols fp32. 592 persistent CTAs (exactly 4 per SM on the
// 148-SM GB300), 256 threads each, 27-28 rows per CTA. Each loop iteration
// issues the NEXT row's streaming loads before reducing/storing the current
// row, so the DRAM pipe never drains across the reduce barrier.

#define ROWS 16384
#define VEC_PER_ROW 1024           // 4096 floats / 4
#define THREADS 256
#define VPT 4                      // float4 per thread per row
#define GRID 592                   // 148 SMs * 4 CTAs
#define NWARPS (THREADS / 32)

__global__ __launch_bounds__(THREADS, 4)
void l2norm_persist_kernel(const float4* __restrict__ in, float4* __restrict__ out) {
    const int t = threadIdx.x;
    __shared__ float warp_sum[2][NWARPS];

    int row = blockIdx.x;
    size_t base = (size_t)row * VEC_PER_ROW;

    // Prologue: load first row.
    float4 v[VPT];
#pragma unroll
    for (int i = 0; i < VPT; i++) v[i] = __ldcs(&in[base + t + i * THREADS]);

    int parity = 0;
    while (true) {
        const int next_row = row + GRID;
        const bool has_next = next_row < ROWS;
        const size_t next_base = (size_t)next_row * VEC_PER_ROW;

        // Issue next row's loads FIRST so they fly during the reduce/barrier.
        float4 w[VPT];
        if (has_next) {
#pragma unroll
            for (int i = 0; i < VPT; i++) w[i] = __ldcs(&in[next_base + t + i * THREADS]);
        }

        // Sum of squares for current row (its loads completed ~a full row ago).
        float ss = 0.0f;
#pragma unroll
        for (int i = 0; i < VPT; i++) {
            ss = fmaf(v[i].x, v[i].x, ss);
            ss = fmaf(v[i].y, v[i].y, ss);
            ss = fmaf(v[i].z, v[i].z, ss);
            ss = fmaf(v[i].w, v[i].w, ss);
        }
#pragma unroll
        for (int o = 16; o > 0; o >>= 1) ss += __shfl_xor_sync(0xffffffffu, ss, o);

        if ((t & 31) == 0) warp_sum[parity][t >> 5] = ss;
        __syncthreads();

        float tot = 0.0f;
#pragma unroll
        for (int wi = 0; wi < NWARPS; wi++) tot += warp_sum[parity][wi];
        const float inv = rsqrtf(tot);

        // Scale + streaming store of current row.
#pragma unroll
        for (int i = 0; i < VPT; i++) {
            float4 o4;
            o4.x = v[i].x * inv;
            o4.y = v[i].y * inv;
            o4.z = v[i].z * inv;
            o4.w = v[i].w * inv;
            __stcs(&out[base + t + i * THREADS], o4);
        }

        if (!has_next) break;
        row = next_row;
        base = next_base;
#pragma unroll
        for (int i = 0; i < VPT; i++) v[i] = w[i];
        parity ^= 1;
    }
}

extern "C" void kernel_launch(void* const* d_in, const int* in_sizes, int n_in,
                              void* d_out, int out_size) {
    const float4* in = (const float4*)d_in[0];
    float4* out = (float4*)d_out;
    l2norm_persist_kernel<<<GRID, THREADS>>>(in, out);
}

// round 8
// speedup vs baseline: 1.0987x; 1.0987x over previous
#include <cuda_runtime.h>

// Per-row L2 normalization: out[r,:] = in[r,:] * rsqrt(sum(in[r,:]^2))
// 16384 rows x 4096 cols fp32. One 128-thread CTA per row: each thread loads
// 8x float4 (32 data regs) held in registers — single HBM read. Reduce is a
// warp shfl tree + 4-word smem combine across only 4 warps. Streaming (.cs)
// loads/stores since neither stream is reused. Non-persistent grid keeps
// hardware load balancing.

#define ROWS 16384
#define VEC_PER_ROW 1024           // 4096 floats / 4
#define THREADS 128
#define VPT (VEC_PER_ROW / THREADS)  // 8 float4 per thread
#define NWARPS (THREADS / 32)        // 4

__global__ __launch_bounds__(THREADS)
void l2norm_row128_kernel(const float4* __restrict__ in, float4* __restrict__ out) {
    const int row = blockIdx.x;
    const size_t base = (size_t)row * VEC_PER_ROW;
    const int t = threadIdx.x;

    // Front-batched streaming loads: 8 independent LDG.128.CS.
    float4 v[VPT];
#pragma unroll
    for (int i = 0; i < VPT; i++) {
        v[i] = __ldcs(&in[base + t + i * THREADS]);
    }

    // Per-thread sum of squares.
    float ss = 0.0f;
#pragma unroll
    for (int i = 0; i < VPT; i++) {
        ss = fmaf(v[i].x, v[i].x, ss);
        ss = fmaf(v[i].y, v[i].y, ss);
        ss = fmaf(v[i].z, v[i].z, ss);
        ss = fmaf(v[i].w, v[i].w, ss);
    }

    // Warp reduce.
#pragma unroll
    for (int o = 16; o > 0; o >>= 1) {
        ss += __shfl_xor_sync(0xffffffffu, ss, o);
    }

    // Cross-warp combine over only 4 warps.
    __shared__ float warp_sum[NWARPS];
    if ((t & 31) == 0) warp_sum[t >> 5] = ss;
    __syncthreads();

    float tot = 0.0f;
#pragma unroll
    for (int w = 0; w < NWARPS; w++) tot += warp_sum[w];

    const float inv = rsqrtf(tot);

    // Scale + streaming store.
#pragma unroll
    for (int i = 0; i < VPT; i++) {
        float4 o4;
        o4.x = v[i].x * inv;
        o4.y = v[i].y * inv;
        o4.z = v[i].z * inv;
        o4.w = v[i].w * inv;
        __stcs(&out[base + t + i * THREADS], o4);
    }
}

extern "C" void kernel_launch(void* const* d_in, const int* in_sizes, int n_in,
                              void* d_out, int out_size) {
    const float4* in = (const float4*)d_in[0];
    float4* out = (float4*)d_out;
    l2norm_row128_kernel<<<ROWS, THREADS>>>(in, out);
}